// round 3
// baseline (speedup 1.0000x reference)
#include <cuda_runtime.h>

// Problem constants (match reference setup_inputs)
#define D    128
#define D4   32          // D/4 float4s per row
#define TE   64          // rows per block tile
#define NT   128         // threads per block
#define NMAX 100000      // N_NODES
#define LN_EPS 1e-5f

// ---------------- static device scratch (no allocations allowed) ----------------
__device__ float g_wt_efeat[D * D];   // transposed [k][n]
__device__ float g_wt_src[D * D];
__device__ float g_wt_dst[D * D];
__device__ float g_wt2[D * D];
__device__ float g_psrc[(size_t)NMAX * D];   // src node projections
__device__ float g_pdst[(size_t)NMAX * D];   // dst node projections (+b1)

// ---------------- weight transpose: w[n][k] -> wt[k][n] ----------------
__global__ void transpose_weights(const float* __restrict__ w_efeat,
                                  const float* __restrict__ w_src,
                                  const float* __restrict__ w_dst,
                                  const float* __restrict__ w2) {
    const float* src;
    float* dst;
    switch (blockIdx.x) {
        case 0:  src = w_efeat; dst = g_wt_efeat; break;
        case 1:  src = w_src;   dst = g_wt_src;   break;
        case 2:  src = w_dst;   dst = g_wt_dst;   break;
        default: src = w2;      dst = g_wt2;      break;
    }
    for (int i = threadIdx.x; i < D * D; i += blockDim.x) {
        int k = i >> 7;
        int n = i & 127;
        dst[i] = src[n * D + k];
    }
}

// 8x8 micro-tile GEMM inner loop over full K=128 from smem tile As and
// K-major weight wt; accumulates into acc[8][8].
__device__ __forceinline__ void gemm_8x8(const float (*As)[D],
                                         const float* __restrict__ wt,
                                         int m0, int n0, float acc[8][8]) {
    for (int k0 = 0; k0 < D; k0 += 4) {
        float4 a4[8];
        #pragma unroll
        for (int i = 0; i < 8; i++)
            a4[i] = *(const float4*)&As[m0 + i][k0];   // 2 addrs/warp -> broadcast
        #pragma unroll
        for (int kk = 0; kk < 4; kk++) {
            float4 w0 = __ldg((const float4*)&wt[(k0 + kk) * D + n0]);
            float4 w1 = __ldg((const float4*)&wt[(k0 + kk) * D + n0 + 4]);
            float wv[8] = {w0.x, w0.y, w0.z, w0.w, w1.x, w1.y, w1.z, w1.w};
            #pragma unroll
            for (int i = 0; i < 8; i++) {
                float av = ((const float*)&a4[i])[kk];
                #pragma unroll
                for (int j = 0; j < 8; j++)
                    acc[i][j] = fmaf(av, wv[j], acc[i][j]);
            }
        }
    }
}

// ---------------- node projection GEMM: out[m][n] = in[m][:] @ wt (+bias) ----------------
__global__ __launch_bounds__(NT, 4) void proj_kernel(const float* __restrict__ in,
                                                     const float* __restrict__ bias,
                                                     int sel, int M) {
    const float* __restrict__ wt  = sel ? g_wt_dst : g_wt_src;
    float* __restrict__       out = sel ? g_pdst   : g_psrc;

    __shared__ float As[TE][D];
    const int tid = threadIdx.x;
    const int ng  = tid & 15;     // 16 n-groups of 8 cols
    const int mg  = tid >> 4;     // 8 m-groups of 8 rows
    const int m0  = mg * 8;
    const int n0  = ng * 8;
    const int r0  = blockIdx.x * TE;
    int rows = M - r0; if (rows > TE) rows = TE;

    for (int i = tid; i < TE * D4; i += NT) {
        int r = i >> 5, c = i & 31;
        float4 v = make_float4(0.f, 0.f, 0.f, 0.f);
        if (r < rows) v = ((const float4*)in)[(size_t)(r0 + r) * D4 + c];
        *(((float4*)&As[r][0]) + c) = v;
    }
    __syncthreads();

    float acc[8][8];
    if (bias) {
        float4 b0 = __ldg((const float4*)&bias[n0]);
        float4 b1 = __ldg((const float4*)&bias[n0 + 4]);
        float bv[8] = {b0.x, b0.y, b0.z, b0.w, b1.x, b1.y, b1.z, b1.w};
        #pragma unroll
        for (int i = 0; i < 8; i++)
            #pragma unroll
            for (int j = 0; j < 8; j++) acc[i][j] = bv[j];
    } else {
        #pragma unroll
        for (int i = 0; i < 8; i++)
            #pragma unroll
            for (int j = 0; j < 8; j++) acc[i][j] = 0.f;
    }

    gemm_8x8(As, wt, m0, n0, acc);

    #pragma unroll
    for (int i = 0; i < 8; i++) {
        int r = r0 + m0 + i;
        if (r < M) {
            ((float4*)out)[(size_t)r * D4 + (n0 >> 2)]     =
                make_float4(acc[i][0], acc[i][1], acc[i][2], acc[i][3]);
            ((float4*)out)[(size_t)r * D4 + (n0 >> 2) + 1] =
                make_float4(acc[i][4], acc[i][5], acc[i][6], acc[i][7]);
        }
    }
}

// ---------------- fused edge kernel: GEMM1 + gather + SiLU + GEMM2 + LayerNorm ----------------
__global__ __launch_bounds__(NT, 4) void edge_kernel(const float* __restrict__ efeat,
                                                     const int* __restrict__ src_idx,
                                                     const int* __restrict__ dst_idx,
                                                     const float* __restrict__ b2,
                                                     const float* __restrict__ gamma,
                                                     const float* __restrict__ beta,
                                                     float* __restrict__ out, int E) {
    __shared__ float As[TE][D];
    const int tid = threadIdx.x;
    const int ng  = tid & 15;
    const int mg  = tid >> 4;
    const int m0  = mg * 8;
    const int n0  = ng * 8;
    const int e0  = blockIdx.x * TE;
    int rows = E - e0; if (rows > TE) rows = TE;

    // stage efeat tile
    for (int i = tid; i < TE * D4; i += NT) {
        int r = i >> 5, c = i & 31;
        float4 v = make_float4(0.f, 0.f, 0.f, 0.f);
        if (r < rows) v = ((const float4*)efeat)[(size_t)(e0 + r) * D4 + c];
        *(((float4*)&As[r][0]) + c) = v;
    }
    __syncthreads();

    float acc[8][8];
    #pragma unroll
    for (int i = 0; i < 8; i++)
        #pragma unroll
        for (int j = 0; j < 8; j++) acc[i][j] = 0.f;

    // GEMM1: t = efeat @ w_efeat^T
    gemm_8x8(As, g_wt_efeat, m0, n0, acc);

    // gather node projections (L2-resident) and add
    #pragma unroll
    for (int i = 0; i < 8; i++) {
        int e = e0 + m0 + i;
        if (e < E) {
            int s = __ldg(&src_idx[e]);
            int d = __ldg(&dst_idx[e]);
            float4 ps0 = __ldg((const float4*)&g_psrc[(size_t)s * D + n0]);
            float4 ps1 = __ldg((const float4*)&g_psrc[(size_t)s * D + n0 + 4]);
            float4 pd0 = __ldg((const float4*)&g_pdst[(size_t)d * D + n0]);
            float4 pd1 = __ldg((const float4*)&g_pdst[(size_t)d * D + n0 + 4]);
            acc[i][0] += ps0.x + pd0.x;  acc[i][1] += ps0.y + pd0.y;
            acc[i][2] += ps0.z + pd0.z;  acc[i][3] += ps0.w + pd0.w;
            acc[i][4] += ps1.x + pd1.x;  acc[i][5] += ps1.y + pd1.y;
            acc[i][6] += ps1.z + pd1.z;  acc[i][7] += ps1.w + pd1.w;
        }
    }

    // SiLU -> smem (reuse As as U tile)
    __syncthreads();
    #pragma unroll
    for (int i = 0; i < 8; i++) {
        float u[8];
        #pragma unroll
        for (int j = 0; j < 8; j++)
            u[j] = acc[i][j] / (1.f + __expf(-acc[i][j]));
        *(float4*)&As[m0 + i][n0]     = make_float4(u[0], u[1], u[2], u[3]);
        *(float4*)&As[m0 + i][n0 + 4] = make_float4(u[4], u[5], u[6], u[7]);
    }
    __syncthreads();

    // GEMM2: h = silu(t) @ w2^T + b2
    {
        float4 b0 = __ldg((const float4*)&b2[n0]);
        float4 b1 = __ldg((const float4*)&b2[n0 + 4]);
        float bv[8] = {b0.x, b0.y, b0.z, b0.w, b1.x, b1.y, b1.z, b1.w};
        #pragma unroll
        for (int i = 0; i < 8; i++)
            #pragma unroll
            for (int j = 0; j < 8; j++) acc[i][j] = bv[j];
    }
    gemm_8x8(As, g_wt2, m0, n0, acc);

    // LayerNorm: rows are split over the 16 lanes sharing an m-group
    // (half-warp). Reduce with xor-shfl offsets 8,4,2,1.
    float4 g0 = __ldg((const float4*)&gamma[n0]);
    float4 g1 = __ldg((const float4*)&gamma[n0 + 4]);
    float4 be0 = __ldg((const float4*)&beta[n0]);
    float4 be1 = __ldg((const float4*)&beta[n0 + 4]);
    float gm[8] = {g0.x, g0.y, g0.z, g0.w, g1.x, g1.y, g1.z, g1.w};
    float bt[8] = {be0.x, be0.y, be0.z, be0.w, be1.x, be1.y, be1.z, be1.w};

    #pragma unroll
    for (int i = 0; i < 8; i++) {
        float s = 0.f;
        #pragma unroll
        for (int j = 0; j < 8; j++) s += acc[i][j];
        #pragma unroll
        for (int o = 8; o; o >>= 1) s += __shfl_xor_sync(0xffffffffu, s, o);
        float mean = s * (1.f / D);

        float q = 0.f;
        #pragma unroll
        for (int j = 0; j < 8; j++) {
            float dlt = acc[i][j] - mean;
            q += dlt * dlt;
        }
        #pragma unroll
        for (int o = 8; o; o >>= 1) q += __shfl_xor_sync(0xffffffffu, q, o);
        float rstd = rsqrtf(q * (1.f / D) + LN_EPS);

        int e = e0 + m0 + i;
        if (e < E) {
            float v[8];
            #pragma unroll
            for (int j = 0; j < 8; j++)
                v[j] = (acc[i][j] - mean) * rstd * gm[j] + bt[j];
            ((float4*)out)[(size_t)e * D4 + (n0 >> 2)]     =
                make_float4(v[0], v[1], v[2], v[3]);
            ((float4*)out)[(size_t)e * D4 + (n0 >> 2) + 1] =
                make_float4(v[4], v[5], v[6], v[7]);
        }
    }
}

// ---------------- launch ----------------
extern "C" void kernel_launch(void* const* d_in, const int* in_sizes, int n_in,
                              void* d_out, int out_size) {
    const float* efeat    = (const float*)d_in[0];
    const float* src_feat = (const float*)d_in[1];
    const float* dst_feat = (const float*)d_in[2];
    const int*   src_idx  = (const int*)d_in[3];
    const int*   dst_idx  = (const int*)d_in[4];
    const float* w_efeat  = (const float*)d_in[5];
    const float* w_src    = (const float*)d_in[6];
    const float* w_dst    = (const float*)d_in[7];
    const float* b1       = (const float*)d_in[8];
    const float* w2       = (const float*)d_in[9];
    const float* b2       = (const float*)d_in[10];
    const float* ln_gamma = (const float*)d_in[11];
    const float* ln_beta  = (const float*)d_in[12];

    const int E = in_sizes[0] / D;
    const int N = in_sizes[1] / D;

    transpose_weights<<<4, 256>>>(w_efeat, w_src, w_dst, w2);
    proj_kernel<<<(N + TE - 1) / TE, NT>>>(src_feat, nullptr, 0, N);
    proj_kernel<<<(N + TE - 1) / TE, NT>>>(dst_feat, b1, 1, N);
    edge_kernel<<<(E + TE - 1) / TE, NT>>>(efeat, src_idx, dst_idx,
                                           b2, ln_gamma, ln_beta,
                                           (float*)d_out, E);
}

// round 5
// speedup vs baseline: 1.1710x; 1.1710x over previous
#include <cuda_runtime.h>
#include <mma.h>
#include <cstdint>

using namespace nvcuda;

#define D      128
#define LDT    132           // padded smem leading dim (floats)
#define NT     256           // threads per block (8 warps)
#define NWARP  8
#define ROWS   16            // rows per warp strip
#define GRID   148
#define LN_EPS 1e-5f
#define NMAX   100000

// smem: W1 [128][132], W2 [128][132], per-warp A strips [8][16][132]
#define W_TILE_F   (D * LDT)                  // 16896 floats
#define A_STRIP_F  (ROWS * LDT)               // 2112 floats
#define OFF_W1     0
#define OFF_W2     (W_TILE_F)
#define OFF_A      (2 * W_TILE_F)
#define SMEM_F     (2 * W_TILE_F + NWARP * A_STRIP_F)
#define SMEM_BYTES (SMEM_F * 4)

// ---------------- static device scratch (no allocations allowed) ----------------
__device__ float g_psrc[(size_t)NMAX * D];
__device__ float g_pdst[(size_t)NMAX * D];

__device__ __forceinline__ float tf32r(float x) { return wmma::__float_to_tf32(x); }

// stage a [N=128,K=128] row-major weight into padded smem, tf32-rounded.
// Ws[n*LDT + k]; as col-major B (k row, n col) with ldm=LDT.
__device__ __forceinline__ void stage_weight(float* Ws, const float* __restrict__ w,
                                             int tid) {
    #pragma unroll
    for (int it = 0; it < (D * 32) / NT; it++) {
        int i = it * NT + tid;
        int r = i >> 5, c4 = i & 31;
        float4 v = ((const float4*)w)[i];
        v.x = tf32r(v.x); v.y = tf32r(v.y); v.z = tf32r(v.z); v.w = tf32r(v.w);
        *(float4*)(Ws + r * LDT + c4 * 4) = v;
    }
}

// one 16x128 GEMM over K=128: acc[8] += A(16xK) * B(KxN)
__device__ __forceinline__ void gemm_strip(
        const float* As, const float* Ws,
        wmma::fragment<wmma::accumulator, 16, 16, 8, float> (&c)[8]) {
    #pragma unroll
    for (int k = 0; k < 16; k++) {
        wmma::fragment<wmma::matrix_a, 16, 16, 8, wmma::precision::tf32,
                       wmma::row_major> a;
        wmma::load_matrix_sync(a, As + k * 8, LDT);
        #pragma unroll
        for (int n = 0; n < 8; n++) {
            wmma::fragment<wmma::matrix_b, 16, 16, 8, wmma::precision::tf32,
                           wmma::col_major> b;
            wmma::load_matrix_sync(b, Ws + n * 16 * LDT + k * 8, LDT);
            wmma::mma_sync(c[n], a, b, c[n]);
        }
    }
}

// stage ROWS x 128 fp32 rows from global (row-major) into warp strip, tf32-rounded
__device__ __forceinline__ void stage_strip(float* As, const float* __restrict__ src,
                                            long r0, long Mlim, int lane) {
    #pragma unroll
    for (int r = 0; r < ROWS; r++) {
        long m = r0 + r;
        float4 v = make_float4(0.f, 0.f, 0.f, 0.f);
        if (m < Mlim) v = ((const float4*)src)[m * 32 + lane];
        v.x = tf32r(v.x); v.y = tf32r(v.y); v.z = tf32r(v.z); v.w = tf32r(v.w);
        *(float4*)(As + r * LDT + lane * 4) = v;
    }
}

// ======================= node projection kernel =======================
__global__ __launch_bounds__(NT, 1) void proj_kernel(const float* __restrict__ src_feat,
                                                     const float* __restrict__ dst_feat,
                                                     const float* __restrict__ w_src,
                                                     const float* __restrict__ w_dst,
                                                     const float* __restrict__ b1,
                                                     int N) {
    extern __shared__ float sm[];
    const int tid = threadIdx.x, wid = tid >> 5, lane = tid & 31;
    stage_weight(sm + OFF_W1, w_src, tid);
    stage_weight(sm + OFF_W2, w_dst, tid);
    __syncthreads();

    float* As = sm + OFF_A + wid * A_STRIP_F;
    const int ns = (N + ROWS - 1) / ROWS;
    const int gw = blockIdx.x * NWARP + wid;

    const int row = lane >> 1;
    const int c0  = (lane & 1) * 64;

    for (int sIdx = gw; sIdx < 2 * ns; sIdx += GRID * NWARP) {
        const int sel = (sIdx >= ns);
        const int st  = sel ? (sIdx - ns) : sIdx;
        const long r0 = (long)st * ROWS;
        const float* in = sel ? dst_feat : src_feat;
        float* outp = sel ? g_pdst : g_psrc;

        stage_strip(As, in, r0, N, lane);

        wmma::fragment<wmma::accumulator, 16, 16, 8, float> c[8];
        #pragma unroll
        for (int n = 0; n < 8; n++) wmma::fill_fragment(c[n], 0.f);
        gemm_strip(As, sel ? (sm + OFF_W2) : (sm + OFF_W1), c);
        #pragma unroll
        for (int n = 0; n < 8; n++)
            wmma::store_matrix_sync(As + n * 16, c[n], LDT, wmma::mem_row_major);
        __syncwarp();

        long m = r0 + row;
        if (m < N) {
            #pragma unroll
            for (int g = 0; g < 16; g++) {
                float4 v = *(float4*)(As + row * LDT + c0 + g * 4);
                if (sel) {
                    float4 bb = __ldg((const float4*)&b1[c0 + g * 4]);
                    v.x += bb.x; v.y += bb.y; v.z += bb.z; v.w += bb.w;
                }
                ((float4*)outp)[m * 32 + (c0 >> 2) + g] = v;
            }
        }
        __syncwarp();
    }
}

// ======================= fused edge kernel =======================
__global__ __launch_bounds__(NT, 1) void edge_kernel(const float* __restrict__ efeat,
                                                     const int* __restrict__ src_idx,
                                                     const int* __restrict__ dst_idx,
                                                     const float* __restrict__ w_efeat,
                                                     const float* __restrict__ w2g,
                                                     const float* __restrict__ b2,
                                                     const float* __restrict__ gamma,
                                                     const float* __restrict__ beta,
                                                     float* __restrict__ out, int E) {
    extern __shared__ float sm[];
    const int tid = threadIdx.x, wid = tid >> 5, lane = tid & 31;
    stage_weight(sm + OFF_W1, w_efeat, tid);
    stage_weight(sm + OFF_W2, w2g, tid);
    __syncthreads();

    float* As = sm + OFF_A + wid * A_STRIP_F;
    const int ns = (E + ROWS - 1) / ROWS;
    const int gw = blockIdx.x * NWARP + wid;

    const int row = lane >> 1;          // 0..15: row within strip
    const int c0  = (lane & 1) * 64;    // column half

    for (int sIdx = gw; sIdx < ns; sIdx += GRID * NWARP) {
        const long e0 = (long)sIdx * ROWS;

        // ---- stage efeat strip ----
        stage_strip(As, efeat, e0, E, lane);

        // ---- GEMM1 ----
        wmma::fragment<wmma::accumulator, 16, 16, 8, float> c[8];
        #pragma unroll
        for (int n = 0; n < 8; n++) wmma::fill_fragment(c[n], 0.f);
        gemm_strip(As, sm + OFF_W1, c);
        #pragma unroll
        for (int n = 0; n < 8; n++)
            wmma::store_matrix_sync(As + n * 16, c[n], LDT, wmma::mem_row_major);
        __syncwarp();

        // ---- epilogue1: gather + SiLU -> tf32, back into strip ----
        {
            long e = e0 + row;
            bool valid = (e < E);
            const float4* ps = nullptr;
            const float4* pd = nullptr;
            if (valid) {
                int s  = __ldg(&src_idx[e]);
                int dn = __ldg(&dst_idx[e]);
                ps = (const float4*)&g_psrc[(size_t)s * D + c0];
                pd = (const float4*)&g_pdst[(size_t)dn * D + c0];
            }
            #pragma unroll
            for (int g = 0; g < 16; g++) {
                float4 v = *(float4*)(As + row * LDT + c0 + g * 4);
                if (valid) {
                    float4 a = __ldg(ps + g);
                    float4 b = __ldg(pd + g);
                    v.x += a.x + b.x; v.y += a.y + b.y;
                    v.z += a.z + b.z; v.w += a.w + b.w;
                }
                v.x = tf32r(v.x / (1.f + __expf(-v.x)));
                v.y = tf32r(v.y / (1.f + __expf(-v.y)));
                v.z = tf32r(v.z / (1.f + __expf(-v.z)));
                v.w = tf32r(v.w / (1.f + __expf(-v.w)));
                *(float4*)(As + row * LDT + c0 + g * 4) = v;
            }
        }
        __syncwarp();

        // ---- GEMM2 ----
        #pragma unroll
        for (int n = 0; n < 8; n++) wmma::fill_fragment(c[n], 0.f);
        gemm_strip(As, sm + OFF_W2, c);
        #pragma unroll
        for (int n = 0; n < 8; n++)
            wmma::store_matrix_sync(As + n * 16, c[n], LDT, wmma::mem_row_major);
        __syncwarp();

        // ---- epilogue2: +b2, LayerNorm, store ----
        {
            // pass 1: partial moments over this lane's 64 columns
            float S = 0.f, Q = 0.f;
            #pragma unroll
            for (int g = 0; g < 16; g++) {
                float4 v = *(float4*)(As + row * LDT + c0 + g * 4);
                float4 bb = __ldg((const float4*)&b2[c0 + g * 4]);
                v.x += bb.x; v.y += bb.y; v.z += bb.z; v.w += bb.w;
                S += v.x + v.y + v.z + v.w;
                Q += v.x * v.x + v.y * v.y + v.z * v.z + v.w * v.w;
            }
            S += __shfl_xor_sync(0xffffffffu, S, 1);
            Q += __shfl_xor_sync(0xffffffffu, Q, 1);
            float mean = S * (1.f / D);
            float var  = Q * (1.f / D) - mean * mean;
            float rstd = rsqrtf(var + LN_EPS);

            long e = e0 + row;
            if (e < E) {
                #pragma unroll
                for (int g = 0; g < 16; g++) {
                    float4 v = *(float4*)(As + row * LDT + c0 + g * 4);
                    float4 bb = __ldg((const float4*)&b2[c0 + g * 4]);
                    float4 gm = __ldg((const float4*)&gamma[c0 + g * 4]);
                    float4 be = __ldg((const float4*)&beta[c0 + g * 4]);
                    float4 o;
                    o.x = (v.x + bb.x - mean) * rstd * gm.x + be.x;
                    o.y = (v.y + bb.y - mean) * rstd * gm.y + be.y;
                    o.z = (v.z + bb.z - mean) * rstd * gm.z + be.z;
                    o.w = (v.w + bb.w - mean) * rstd * gm.w + be.w;
                    ((float4*)out)[e * 32 + (c0 >> 2) + g] = o;
                }
            }
        }
        __syncwarp();
    }
}

// ---------------- launch ----------------
extern "C" void kernel_launch(void* const* d_in, const int* in_sizes, int n_in,
                              void* d_out, int out_size) {
    const float* efeat    = (const float*)d_in[0];
    const float* src_feat = (const float*)d_in[1];
    const float* dst_feat = (const float*)d_in[2];
    const int*   src_idx  = (const int*)d_in[3];
    const int*   dst_idx  = (const int*)d_in[4];
    const float* w_efeat  = (const float*)d_in[5];
    const float* w_src    = (const float*)d_in[6];
    const float* w_dst    = (const float*)d_in[7];
    const float* b1       = (const float*)d_in[8];
    const float* w2       = (const float*)d_in[9];
    const float* b2       = (const float*)d_in[10];
    const float* ln_gamma = (const float*)d_in[11];
    const float* ln_beta  = (const float*)d_in[12];

    const int E = in_sizes[0] / D;
    const int N = in_sizes[1] / D;

    cudaFuncSetAttribute(proj_kernel, cudaFuncAttributeMaxDynamicSharedMemorySize, SMEM_BYTES);
    cudaFuncSetAttribute(edge_kernel, cudaFuncAttributeMaxDynamicSharedMemorySize, SMEM_BYTES);

    proj_kernel<<<GRID, NT, SMEM_BYTES>>>(src_feat, dst_feat, w_src, w_dst, b1, N);
    edge_kernel<<<GRID, NT, SMEM_BYTES>>>(efeat, src_idx, dst_idx, w_efeat, w2,
                                          b2, ln_gamma, ln_beta, (float*)d_out, E);
}